// round 16
// baseline (speedup 1.0000x reference)
#include <cuda_runtime.h>
#include <cstdint>
#include <math.h>

#define BB 4
#define NN 8192
#define ROWS (BB*NN)     // 32768
#define CIN 64
#define MID 64
#define COUT 128
#define KNB 16
#define NBIN 256
#define CHK 32
#define NCHK (NN/CHK)    // 256
#define EPSBN 1e-5f
#define FULLM 0xffffffffu

// ---------------- scratch ----------------
__device__ float4 g_c4[ROWS];                 // (x,y,z,|c|^2)
__device__ int    g_cnt[BB][NCHK][NBIN];
__device__ int    g_off[BB][NCHK][NBIN];      // chunk-cumulative per bin (no binStart)
__device__ int    g_bs[BB][NBIN];             // bin start (exclusive prefix)
__device__ float4 g_sc4[ROWS];                // x-bin-sorted coords
__device__ int    g_sidx[ROWS];               // sorted pos -> original local idx
__device__ int   g_knn[ROWS*KNB];
__device__ float g_X [ROWS*CIN];
__device__ float g_Y1[ROWS*MID];
__device__ float g_Ag[ROWS*MID];
__device__ float g_Ya[ROWS*MID];
__device__ float g_Y2[ROWS*COUT];
__device__ float g_Ps1[256*MID],  g_Pq1[256*MID];
__device__ float g_Psa[256*MID],  g_Pqa[256*MID];
__device__ float g_Ps2[256*COUT], g_Pq2[256*COUT];
__device__ float g_A1[MID],  g_C1[MID];
__device__ float g_Aa[MID],  g_Ca[MID];
__device__ float g_A2[COUT], g_C2[COUT];

__device__ __forceinline__ int binof(float x) {
    int b = (int)floorf((x + 4.0f) * 32.0f);
    return min(NBIN-1, max(0, b));
}

// ---------------- prep + per-chunk bin counts ----------------
__global__ void __launch_bounds__(256) k_prepcount(const float* __restrict__ coords)
{
    const int ig = blockIdx.x * 256 + threadIdx.x;
    const int batch = ig >> 13;
    const int il = ig & (NN-1);
    const int tid = threadIdx.x;
    const int lane = tid & 31;
    const int chunk0 = ((blockIdx.x & 31) * 256) >> 5;   // first chunk this block covers

    // zero this block's 8 chunks of counts
    for (int j = tid; j < 8*NBIN; j += 256)
        g_cnt[batch][chunk0 + (j >> 8)][j & (NBIN-1)] = 0;
    __syncthreads();

    const float x = coords[ig*3+0], y = coords[ig*3+1], z = coords[ig*3+2];
    g_c4[ig] = make_float4(x, y, z, x*x + y*y + z*z);

    const int b = binof(x);
    const unsigned mask = __match_any_sync(FULLM, b);
    const int rank = __popc(mask & ((1u << lane) - 1u));
    if (rank == 0)
        g_cnt[batch][il >> 5][b] = __popc(mask);
}

// ---------------- per-batch: chunk-cumulative offsets + bin starts ----------------
__global__ void __launch_bounds__(NBIN) k_binscan()
{
    const int batch = blockIdx.x;
    const int bin = threadIdx.x;
    int run = 0;
#pragma unroll 4
    for (int c = 0; c < NCHK; ++c) {
        const int v = g_cnt[batch][c][bin];
        g_off[batch][c][bin] = run;
        run += v;
    }
    __shared__ int a[NBIN];
    a[bin] = run;
    __syncthreads();
    // Hillis-Steele inclusive scan over bins
    for (int off = 1; off < NBIN; off <<= 1) {
        const int v = a[bin] + ((bin >= off) ? a[bin-off] : 0);
        __syncthreads();
        a[bin] = v;
        __syncthreads();
    }
    g_bs[batch][bin] = (bin > 0) ? a[bin-1] : 0;
}

// ---------------- scatter into x-bin-sorted order (stable by index) ----------------
__global__ void __launch_bounds__(256) k_scatter()
{
    const int ig = blockIdx.x * 256 + threadIdx.x;
    const int batch = ig >> 13;
    const int il = ig & (NN-1);
    const int lane = threadIdx.x & 31;

    const float4 c = g_c4[ig];
    const int b = binof(c.x);
    const unsigned mask = __match_any_sync(FULLM, b);
    const int rank = __popc(mask & ((1u << lane) - 1u));
    const int dst = g_bs[batch][b] + g_off[batch][il >> 5][b] + rank;
    g_sc4[(size_t)batch*NN + dst] = c;
    g_sidx[(size_t)batch*NN + dst] = il;
}

// ---------------- kNN: 2 sorted-adjacent queries/warp, chunked window expansion ----
__global__ void __launch_bounds__(256) k_knn()
{
    const int batch = blockIdx.y;
    const int warp = threadIdx.x >> 5;
    const int lane = threadIdx.x & 31;
    const float4* __restrict__ sc = g_sc4 + (size_t)batch * NN;
    const int*    __restrict__ si = g_sidx + (size_t)batch * NN;

    const int p0 = blockIdx.x * 16 + warp * 2;
    const float4 qa = sc[p0];
    const float4 qb = sc[p0+1];
    const float q0x = -2.0f*qa.x, q0y = -2.0f*qa.y, q0z = -2.0f*qa.z;
    const float q1x = -2.0f*qb.x, q1y = -2.0f*qb.y, q1z = -2.0f*qb.z;

    float kd = 3.0e38f;           // lane's slot of its half's list (shifted distance)
    int   ki = 0;
    float kth0 = 3.0e38f, kth1 = 3.0e38f;

    const int cbase = (p0 >> 5) << 5;   // aligned chunk containing both queries
    int r = cbase;
    int l = cbase - CHK;
    bool rAct = true;
    bool lAct = (l >= 0);

    while (rAct || lAct) {
        // -------- right chunk --------
        if (rAct) {
            const int base = r;
            const float4 c = sc[base + lane];
            const float d0 = fmaf(q0x, c.x, fmaf(q0y, c.y, fmaf(q0z, c.z, c.w)));
            const float d1 = fmaf(q1x, c.x, fmaf(q1y, c.y, fmaf(q1z, c.z, c.w)));
            unsigned m0 = __ballot_sync(FULLM, d0 < kth0);
            unsigned m1 = __ballot_sync(FULLM, d1 < kth1);
            while (m0) {
                const int src = __ffs(m0) - 1; m0 &= m0 - 1;
                const float dn = __shfl_sync(FULLM, d0, src);
                if (dn < kth0) {
                    const int jn = si[base + src];
                    const unsigned le = __ballot_sync(FULLM, kd <= dn) & 0xffffu;
                    const int pos = __popc(le);
                    const float kdp = __shfl_up_sync(FULLM, kd, 1);
                    const int   kip = __shfl_up_sync(FULLM, ki, 1);
                    const bool ins = (lane == pos);
                    const bool shf = (lane > pos) && (lane < KNB);
                    kd = ins ? dn : (shf ? kdp : kd);
                    ki = ins ? jn : (shf ? kip : ki);
                    kth0 = __shfl_sync(FULLM, kd, 15);
                }
            }
            while (m1) {
                const int src = __ffs(m1) - 1; m1 &= m1 - 1;
                const float dn = __shfl_sync(FULLM, d1, src);
                if (dn < kth1) {
                    const int jn = si[base + src];
                    const unsigned hi = __ballot_sync(FULLM, kd <= dn) & 0xffff0000u;
                    const int pos = 16 + __popc(hi);
                    const float kdp = __shfl_up_sync(FULLM, kd, 1);
                    const int   kip = __shfl_up_sync(FULLM, ki, 1);
                    const bool ins = (lane == pos);
                    const bool shf = (lane > pos);
                    kd = ins ? dn : (shf ? kdp : kd);
                    ki = ins ? jn : (shf ? kip : ki);
                    kth1 = __shfl_sync(FULLM, kd, 31);
                }
            }
            r += CHK;
            if (r >= NN) rAct = false;
            else {
                // conservative lower bound on x for all positions >= r
                const int bb = binof(sc[r].x);
                const float edge = (bb == 0) ? -1.0e30f
                                             : ((float)bb * 0.03125f - 4.0f - 1e-5f);
                const float dxa = edge - qa.x;
                const float dxb = edge - qb.x;
                const bool a0 = (dxa <= 0.f) || (dxa*dxa < kth0 + qa.w);
                const bool a1 = (dxb <= 0.f) || (dxb*dxb < kth1 + qb.w);
                rAct = a0 || a1;
            }
        }
        // -------- left chunk --------
        if (lAct) {
            const int base = l;
            const float4 c = sc[base + lane];
            const float d0 = fmaf(q0x, c.x, fmaf(q0y, c.y, fmaf(q0z, c.z, c.w)));
            const float d1 = fmaf(q1x, c.x, fmaf(q1y, c.y, fmaf(q1z, c.z, c.w)));
            unsigned m0 = __ballot_sync(FULLM, d0 < kth0);
            unsigned m1 = __ballot_sync(FULLM, d1 < kth1);
            while (m0) {
                const int src = __ffs(m0) - 1; m0 &= m0 - 1;
                const float dn = __shfl_sync(FULLM, d0, src);
                if (dn < kth0) {
                    const int jn = si[base + src];
                    const unsigned le = __ballot_sync(FULLM, kd <= dn) & 0xffffu;
                    const int pos = __popc(le);
                    const float kdp = __shfl_up_sync(FULLM, kd, 1);
                    const int   kip = __shfl_up_sync(FULLM, ki, 1);
                    const bool ins = (lane == pos);
                    const bool shf = (lane > pos) && (lane < KNB);
                    kd = ins ? dn : (shf ? kdp : kd);
                    ki = ins ? jn : (shf ? kip : ki);
                    kth0 = __shfl_sync(FULLM, kd, 15);
                }
            }
            while (m1) {
                const int src = __ffs(m1) - 1; m1 &= m1 - 1;
                const float dn = __shfl_sync(FULLM, d1, src);
                if (dn < kth1) {
                    const int jn = si[base + src];
                    const unsigned hi = __ballot_sync(FULLM, kd <= dn) & 0xffff0000u;
                    const int pos = 16 + __popc(hi);
                    const float kdp = __shfl_up_sync(FULLM, kd, 1);
                    const int   kip = __shfl_up_sync(FULLM, ki, 1);
                    const bool ins = (lane == pos);
                    const bool shf = (lane > pos);
                    kd = ins ? dn : (shf ? kdp : kd);
                    ki = ins ? jn : (shf ? kip : ki);
                    kth1 = __shfl_sync(FULLM, kd, 31);
                }
            }
            l -= CHK;
            if (l < 0) lAct = false;
            else {
                // conservative upper bound on x for all positions <= l+CHK-1
                const int bb = binof(sc[l + CHK - 1].x);
                const float edge = (bb == NBIN-1) ? 1.0e30f
                                                  : ((float)(bb+1) * 0.03125f - 4.0f + 1e-5f);
                const float dxa = qa.x - edge;
                const float dxb = qb.x - edge;
                const bool a0 = (dxa <= 0.f) || (dxa*dxa < kth0 + qa.w);
                const bool a1 = (dxb <= 0.f) || (dxb*dxb < kth1 + qb.w);
                lAct = a0 || a1;
            }
        }
    }

    const int q0i = si[p0];
    const int q1i = si[p0+1];
    const int qq = (lane >> 4) ? q1i : q0i;
    g_knn[((size_t)(batch*NN + qq))*KNB + (lane & 15)] = ki;
}

// ---------------- gather + mean: one warp per point ----------------
__global__ void __launch_bounds__(256) k_gather(const float* __restrict__ feats)
{
    const int row  = blockIdx.x * 8 + (threadIdx.x >> 5);
    const int lane = threadIdx.x & 31;
    const int b = row >> 13;
    const float* fb = feats + (size_t)b * NN * CIN;
    const int* ip = g_knn + (size_t)row * KNB;

    float2 acc = make_float2(0.f, 0.f);
#pragma unroll
    for (int m = 0; m < KNB; ++m) {
        const int id = ip[m];
        const float2 v = ((const float2*)(fb + (size_t)id * CIN))[lane];
        acc.x += v.x; acc.y += v.y;
    }
    ((float2*)(g_X + (size_t)row * CIN))[lane] =
        make_float2(acc.x * (1.0f/KNB), acc.y * (1.0f/KNB));
}

// ---------------- warp sum ----------------
__device__ __forceinline__ float warp_sum(float v) {
#pragma unroll
    for (int o = 16; o; o >>= 1) v += __shfl_xor_sync(FULLM, v, o);
    return v;
}

// ---------------- MLP1: channel-split x4, chunked x ----------------
__global__ void __launch_bounds__(128) k_mlp1(const float* __restrict__ W,
                                              const float* __restrict__ bias)
{
    __shared__ float Ws[CIN*16];
    __shared__ float wsum[4][16], wsq[4][16];
    const int tid = threadIdx.x;
    const int cg = blockIdx.y;
    for (int i = tid; i < CIN*16; i += 128) {
        const int k = i >> 4, c = i & 15;
        Ws[i] = W[k*MID + cg*16 + c];
    }
    __syncthreads();

    const int r = blockIdx.x * 128 + tid;
    const float4* xp = (const float4*)(g_X + (size_t)r * CIN);
    const float4* W4 = (const float4*)Ws;
    const float4* b4 = (const float4*)(bias + cg*16);

    float4 acc[4];
#pragma unroll
    for (int g = 0; g < 4; ++g) acc[g] = b4[g];

#pragma unroll
    for (int kk = 0; kk < CIN/16; ++kk) {
        float xc[16];
#pragma unroll
        for (int u = 0; u < 4; ++u) {
            const float4 v = xp[kk*4+u];
            xc[4*u]=v.x; xc[4*u+1]=v.y; xc[4*u+2]=v.z; xc[4*u+3]=v.w;
        }
#pragma unroll
        for (int j = 0; j < 16; ++j) {
            const int k = kk*16 + j;
            const float xs = xc[j];
#pragma unroll
            for (int g = 0; g < 4; ++g) {
                const float4 w = W4[k*4+g];
                acc[g].x = fmaf(xs, w.x, acc[g].x);
                acc[g].y = fmaf(xs, w.y, acc[g].y);
                acc[g].z = fmaf(xs, w.z, acc[g].z);
                acc[g].w = fmaf(xs, w.w, acc[g].w);
            }
        }
    }

    const int warp = tid >> 5, lane = tid & 31;
    float4* yp = (float4*)(g_Y1 + (size_t)r * MID + cg*16);
#pragma unroll
    for (int g = 0; g < 4; ++g) {
        yp[g] = acc[g];
        const float vs[4] = {acc[g].x, acc[g].y, acc[g].z, acc[g].w};
#pragma unroll
        for (int u = 0; u < 4; ++u) {
            const float s = warp_sum(vs[u]);
            const float qq = warp_sum(vs[u]*vs[u]);
            if (lane == 0) { wsum[warp][4*g+u] = s; wsq[warp][4*g+u] = qq; }
        }
    }
    __syncthreads();
    if (tid < 16) {
        g_Ps1[blockIdx.x*MID + cg*16 + tid] = wsum[0][tid]+wsum[1][tid]+wsum[2][tid]+wsum[3][tid];
        g_Pq1[blockIdx.x*MID + cg*16 + tid] = wsq [0][tid]+wsq [1][tid]+wsq [2][tid]+wsq [3][tid];
    }
}

// ---------------- BN stats finalize ----------------
__device__ __forceinline__ void stats_mid(const float* Ps, const float* Pq,
                                          const float* g, const float* be,
                                          float* A, float* C)
{
    __shared__ float ss[256], sq[256];
    const int tid = threadIdx.x;
    const int c = tid & (MID-1);
    const int grp = tid >> 6;
    float s = 0.f, q = 0.f;
    const int i0 = grp * 64;
#pragma unroll 4
    for (int i = i0; i < i0 + 64; ++i) { s += Ps[i*MID+c]; q += Pq[i*MID+c]; }
    ss[tid] = s; sq[tid] = q;
    __syncthreads();
    if (tid < MID) {
        s = ss[tid] + ss[tid+64] + ss[tid+128] + ss[tid+192];
        q = sq[tid] + sq[tid+64] + sq[tid+128] + sq[tid+192];
        const float m = s / (float)ROWS;
        const float v = q / (float)ROWS - m*m;
        const float a = g[tid] / sqrtf(v + EPSBN);
        A[tid] = a; C[tid] = be[tid] - m*a;
    }
}
__global__ void k_stats1(const float* __restrict__ g, const float* __restrict__ be)
{ stats_mid(g_Ps1, g_Pq1, g, be, g_A1, g_C1); }
__global__ void k_statsa(const float* __restrict__ g, const float* __restrict__ be)
{ stats_mid(g_Psa, g_Pqa, g, be, g_Aa, g_Ca); }

__global__ void k_stats2(const float* __restrict__ g, const float* __restrict__ be)
{
    __shared__ float ss[512], sq[512];
    const int tid = threadIdx.x;
    const int c = tid & (COUT-1);
    const int grp = tid >> 7;
    float s = 0.f, q = 0.f;
    const int i0 = grp * 64;
#pragma unroll 4
    for (int i = i0; i < i0 + 64; ++i) { s += g_Ps2[i*COUT+c]; q += g_Pq2[i*COUT+c]; }
    ss[tid] = s; sq[tid] = q;
    __syncthreads();
    if (tid < COUT) {
        s = ss[tid] + ss[tid+128] + ss[tid+256] + ss[tid+384];
        q = sq[tid] + sq[tid+128] + sq[tid+256] + sq[tid+384];
        const float m = s / (float)ROWS;
        const float v = q / (float)ROWS - m*m;
        const float a = g[tid] / sqrtf(v + EPSBN);
        g_A2[tid] = a; g_C2[tid] = be[tid] - m*a;
    }
}

// ---------------- MLPa: channel-split x4, chunked x ----------------
__global__ void __launch_bounds__(128) k_mlpa(const float* __restrict__ W,
                                              const float* __restrict__ bias)
{
    __shared__ float Ws[MID*16];
    __shared__ float wsum[4][16], wsq[4][16];
    const int tid = threadIdx.x;
    const int cg = blockIdx.y;
    for (int i = tid; i < MID*16; i += 128) {
        const int k = i >> 4, c = i & 15;
        Ws[i] = W[k*MID + cg*16 + c];
    }
    __syncthreads();

    const int r = blockIdx.x * 128 + tid;
    const float4* yin = (const float4*)(g_Y1 + (size_t)r * MID);
    float4* ap = (float4*)(g_Ag + (size_t)r * MID);
    const float4* W4 = (const float4*)Ws;
    const float4* b4 = (const float4*)(bias + cg*16);

    float4 acc[4];
#pragma unroll
    for (int g = 0; g < 4; ++g) acc[g] = b4[g];

#pragma unroll
    for (int kk = 0; kk < MID/16; ++kk) {
        float xc[16];
#pragma unroll
        for (int u = 0; u < 4; ++u) {
            const int i = kk*4 + u;
            const float4 v = yin[i];
            float z0 = fmaxf(fmaf(g_A1[4*i+0], v.x, g_C1[4*i+0]), 0.f);
            float z1 = fmaxf(fmaf(g_A1[4*i+1], v.y, g_C1[4*i+1]), 0.f);
            float z2 = fmaxf(fmaf(g_A1[4*i+2], v.z, g_C1[4*i+2]), 0.f);
            float z3 = fmaxf(fmaf(g_A1[4*i+3], v.w, g_C1[4*i+3]), 0.f);
            if (cg == 0) ap[i] = make_float4(z0, z1, z2, z3);
            xc[4*u]=z0; xc[4*u+1]=z1; xc[4*u+2]=z2; xc[4*u+3]=z3;
        }
#pragma unroll
        for (int j = 0; j < 16; ++j) {
            const int k = kk*16 + j;
            const float xs = xc[j];
#pragma unroll
            for (int g = 0; g < 4; ++g) {
                const float4 w = W4[k*4+g];
                acc[g].x = fmaf(xs, w.x, acc[g].x);
                acc[g].y = fmaf(xs, w.y, acc[g].y);
                acc[g].z = fmaf(xs, w.z, acc[g].z);
                acc[g].w = fmaf(xs, w.w, acc[g].w);
            }
        }
    }

    const int warp = tid >> 5, lane = tid & 31;
    float4* yp = (float4*)(g_Ya + (size_t)r * MID + cg*16);
#pragma unroll
    for (int g = 0; g < 4; ++g) {
        yp[g] = acc[g];
        const float vs[4] = {acc[g].x, acc[g].y, acc[g].z, acc[g].w};
#pragma unroll
        for (int u = 0; u < 4; ++u) {
            const float s = warp_sum(vs[u]);
            const float qq = warp_sum(vs[u]*vs[u]);
            if (lane == 0) { wsum[warp][4*g+u] = s; wsq[warp][4*g+u] = qq; }
        }
    }
    __syncthreads();
    if (tid < 16) {
        g_Psa[blockIdx.x*MID + cg*16 + tid] = wsum[0][tid]+wsum[1][tid]+wsum[2][tid]+wsum[3][tid];
        g_Pqa[blockIdx.x*MID + cg*16 + tid] = wsq [0][tid]+wsq [1][tid]+wsq [2][tid]+wsq [3][tid];
    }
}

// ---------------- MLP2: channel-split x4, chunked x ----------------
__global__ void __launch_bounds__(128) k_mlp2(const float* __restrict__ W,
                                              const float* __restrict__ bias)
{
    __shared__ float Ws[MID*32];
    __shared__ float wsum[4][32], wsq[4][32];
    const int tid = threadIdx.x;
    const int cg = blockIdx.y;
    for (int i = tid; i < MID*32; i += 128) {
        const int k = i >> 5, c = i & 31;
        Ws[i] = W[k*COUT + cg*32 + c];
    }
    __syncthreads();

    const int r = blockIdx.x * 128 + tid;
    const float4* yin = (const float4*)(g_Ya + (size_t)r * MID);
    const float4* ain = (const float4*)(g_Ag + (size_t)r * MID);
    const float4* W4 = (const float4*)Ws;
    const float4* b4 = (const float4*)(bias + cg*32);

    float4 acc[8];
#pragma unroll
    for (int g = 0; g < 8; ++g) acc[g] = b4[g];

#pragma unroll
    for (int kk = 0; kk < MID/16; ++kk) {
        float xc[16];
#pragma unroll
        for (int u = 0; u < 4; ++u) {
            const int i = kk*4 + u;
            const float4 y = yin[i];
            const float4 a = ain[i];
            float t0 = fmaxf(fmaf(g_Aa[4*i+0], y.x, g_Ca[4*i+0]), 0.f);
            float t1 = fmaxf(fmaf(g_Aa[4*i+1], y.y, g_Ca[4*i+1]), 0.f);
            float t2 = fmaxf(fmaf(g_Aa[4*i+2], y.z, g_Ca[4*i+2]), 0.f);
            float t3 = fmaxf(fmaf(g_Aa[4*i+3], y.w, g_Ca[4*i+3]), 0.f);
            float s0 = 1.0f / (1.0f + expf(-t0));
            float s1 = 1.0f / (1.0f + expf(-t1));
            float s2 = 1.0f / (1.0f + expf(-t2));
            float s3 = 1.0f / (1.0f + expf(-t3));
            xc[4*u+0] = fmaf(a.x, s0, a.x);
            xc[4*u+1] = fmaf(a.y, s1, a.y);
            xc[4*u+2] = fmaf(a.z, s2, a.z);
            xc[4*u+3] = fmaf(a.w, s3, a.w);
        }
#pragma unroll
        for (int j = 0; j < 16; ++j) {
            const int k = kk*16 + j;
            const float xs = xc[j];
#pragma unroll
            for (int g = 0; g < 8; ++g) {
                const float4 w = W4[k*8+g];
                acc[g].x = fmaf(xs, w.x, acc[g].x);
                acc[g].y = fmaf(xs, w.y, acc[g].y);
                acc[g].z = fmaf(xs, w.z, acc[g].z);
                acc[g].w = fmaf(xs, w.w, acc[g].w);
            }
        }
    }

    const int warp = tid >> 5, lane = tid & 31;
    float4* yp = (float4*)(g_Y2 + (size_t)r * COUT + cg*32);
#pragma unroll
    for (int g = 0; g < 8; ++g) {
        yp[g] = acc[g];
        const float vs[4] = {acc[g].x, acc[g].y, acc[g].z, acc[g].w};
#pragma unroll
        for (int u = 0; u < 4; ++u) {
            const float s = warp_sum(vs[u]);
            const float qq = warp_sum(vs[u]*vs[u]);
            if (lane == 0) { wsum[warp][4*g+u] = s; wsq[warp][4*g+u] = qq; }
        }
    }
    __syncthreads();
    if (tid < 32) {
        g_Ps2[blockIdx.x*COUT + cg*32 + tid] = wsum[0][tid]+wsum[1][tid]+wsum[2][tid]+wsum[3][tid];
        g_Pq2[blockIdx.x*COUT + cg*32 + tid] = wsq [0][tid]+wsq [1][tid]+wsq [2][tid]+wsq [3][tid];
    }
}

// ---------------- final ----------------
__global__ void __launch_bounds__(256) k_final(float* __restrict__ out)
{
    const int i = blockIdx.x * 256 + threadIdx.x;
    const int c = i & (COUT-1);
    out[i] = fmaxf(fmaf(g_A2[c], g_Y2[i], g_C2[c]), 0.f);
}

// ---------------- launch ----------------
extern "C" void kernel_launch(void* const* d_in, const int* in_sizes, int n_in,
                              void* d_out, int out_size)
{
    const float* coords = (const float*)d_in[0];
    const float* feats  = (const float*)d_in[1];
    const float* W1  = (const float*)d_in[3];
    const float* b1  = (const float*)d_in[4];
    const float* g1  = (const float*)d_in[5];
    const float* be1 = (const float*)d_in[6];
    const float* Wa  = (const float*)d_in[7];
    const float* ba  = (const float*)d_in[8];
    const float* ga  = (const float*)d_in[9];
    const float* bea = (const float*)d_in[10];
    const float* W2  = (const float*)d_in[11];
    const float* b2  = (const float*)d_in[12];
    const float* g2  = (const float*)d_in[13];
    const float* be2 = (const float*)d_in[14];
    float* out = (float*)d_out;

    k_prepcount<<<ROWS/256, 256>>>(coords);
    k_binscan  <<<BB, NBIN>>>();
    k_scatter  <<<ROWS/256, 256>>>();
    k_knn      <<<dim3(NN/16, BB), 256>>>();   // launch #4 -> profiled
    k_gather   <<<ROWS/8, 256>>>(feats);
    k_mlp1     <<<dim3(256, 4), 128>>>(W1, b1);
    k_stats1   <<<1, 256>>>(g1, be1);
    k_mlpa     <<<dim3(256, 4), 128>>>(Wa, ba);
    k_statsa   <<<1, 256>>>(ga, bea);
    k_mlp2     <<<dim3(256, 4), 128>>>(W2, b2);
    k_stats2   <<<1, 512>>>(g2, be2);
    k_final    <<<(ROWS*COUT)/256, 256>>>(out);
}

// round 17
// speedup vs baseline: 1.0757x; 1.0757x over previous
#include <cuda_runtime.h>
#include <cstdint>
#include <math.h>

#define BB 4
#define NN 8192
#define ROWS (BB*NN)     // 32768
#define CIN 64
#define MID 64
#define COUT 128
#define KNB 16
#define NBIN 256
#define CHK 32
#define NCHK (NN/CHK)    // 256
#define EPSBN 1e-5f
#define FULLM 0xffffffffu

// ---------------- scratch ----------------
__device__ float4 g_c4[ROWS];                 // (x,y,z,-)
__device__ int    g_cnt[BB][NCHK][NBIN];
__device__ int    g_off[BB][NCHK][NBIN];
__device__ int    g_bs[BB][NBIN];
__device__ float4 g_sc4[ROWS];                // x-bin-sorted: (x,y,z, idx_bits)
__device__ int   g_knn[ROWS*KNB];
__device__ float g_X [ROWS*CIN];
__device__ float g_Y1[ROWS*MID];
__device__ float g_Ag[ROWS*MID];
__device__ float g_Ya[ROWS*MID];
__device__ float g_Y2[ROWS*COUT];
__device__ float g_Ps1[256*MID],  g_Pq1[256*MID];
__device__ float g_Psa[256*MID],  g_Pqa[256*MID];
__device__ float g_Ps2[256*COUT], g_Pq2[256*COUT];
__device__ float g_A1[MID],  g_C1[MID];
__device__ float g_Aa[MID],  g_Ca[MID];
__device__ float g_A2[COUT], g_C2[COUT];

__device__ __forceinline__ int binof(float x) {
    int b = (int)floorf((x + 4.0f) * 32.0f);
    return min(NBIN-1, max(0, b));
}

// ---------------- prep + per-chunk bin counts ----------------
__global__ void __launch_bounds__(256) k_prepcount(const float* __restrict__ coords)
{
    const int ig = blockIdx.x * 256 + threadIdx.x;
    const int batch = ig >> 13;
    const int il = ig & (NN-1);
    const int tid = threadIdx.x;
    const int lane = tid & 31;
    const int chunk0 = ((blockIdx.x & 31) * 256) >> 5;

    for (int j = tid; j < 8*NBIN; j += 256)
        g_cnt[batch][chunk0 + (j >> 8)][j & (NBIN-1)] = 0;
    __syncthreads();

    const float x = coords[ig*3+0], y = coords[ig*3+1], z = coords[ig*3+2];
    g_c4[ig] = make_float4(x, y, z, 0.f);

    const int b = binof(x);
    const unsigned mask = __match_any_sync(FULLM, b);
    const int rank = __popc(mask & ((1u << lane) - 1u));
    if (rank == 0)
        g_cnt[batch][il >> 5][b] = __popc(mask);
}

// ---------------- per-batch: chunk-cumulative offsets + bin starts ----------------
__global__ void __launch_bounds__(NBIN) k_binscan()
{
    const int batch = blockIdx.x;
    const int bin = threadIdx.x;
    int run = 0;
#pragma unroll 4
    for (int c = 0; c < NCHK; ++c) {
        const int v = g_cnt[batch][c][bin];
        g_off[batch][c][bin] = run;
        run += v;
    }
    __shared__ int a[NBIN];
    a[bin] = run;
    __syncthreads();
    for (int off = 1; off < NBIN; off <<= 1) {
        const int v = a[bin] + ((bin >= off) ? a[bin-off] : 0);
        __syncthreads();
        a[bin] = v;
        __syncthreads();
    }
    g_bs[batch][bin] = (bin > 0) ? a[bin-1] : 0;
}

// ---------------- scatter into x-bin-sorted order; idx packed in w ----------------
__global__ void __launch_bounds__(256) k_scatter()
{
    const int ig = blockIdx.x * 256 + threadIdx.x;
    const int batch = ig >> 13;
    const int il = ig & (NN-1);
    const int lane = threadIdx.x & 31;

    const float4 c = g_c4[ig];
    const int b = binof(c.x);
    const unsigned mask = __match_any_sync(FULLM, b);
    const int rank = __popc(mask & ((1u << lane) - 1u));
    const int dst = g_bs[batch][b] + g_off[batch][il >> 5][b] + rank;
    g_sc4[(size_t)batch*NN + dst] = make_float4(c.x, c.y, c.z, __int_as_float(il));
}

// ---------------- kNN: sorted window expansion, prefetched, loadless bounds ----------
__global__ void __launch_bounds__(256) k_knn()
{
    const int batch = blockIdx.y;
    const int warp = threadIdx.x >> 5;
    const int lane = threadIdx.x & 31;
    const float4* __restrict__ sc = g_sc4 + (size_t)batch * NN;

    const int p0 = blockIdx.x * 16 + warp * 2;
    const float4 qa = sc[p0];
    const float4 qb = sc[p0+1];
    const int q0i = __float_as_int(qa.w);
    const int q1i = __float_as_int(qb.w);
    const float qaw = fmaf(qa.z, qa.z, fmaf(qa.y, qa.y, qa.x*qa.x));
    const float qbw = fmaf(qb.z, qb.z, fmaf(qb.y, qb.y, qb.x*qb.x));
    const float q0x = -2.0f*qa.x, q0y = -2.0f*qa.y, q0z = -2.0f*qa.z;
    const float q1x = -2.0f*qb.x, q1y = -2.0f*qb.y, q1z = -2.0f*qb.z;

    float kd = 3.0e38f;           // lane's slot of its half's list (shifted distance)
    int   ki = 0;
    float kth0 = 3.0e38f, kth1 = 3.0e38f;

    const int cbase = (p0 >> 5) << 5;
    int r = cbase;
    int l = cbase - CHK;
    bool rAct = true;
    bool lAct = (l >= 0);
    float4 cR = sc[r + lane];
    float4 cL = lAct ? sc[l + lane] : make_float4(0.f,0.f,0.f,0.f);

    while (rAct || lAct) {
        // -------- right chunk --------
        if (rAct) {
            const float4 c = cR;
            const int rn = r + CHK;
            const bool rmore = (rn < NN);
            if (rmore) cR = sc[rn + lane];            // prefetch next
            const float cc = fmaf(c.z, c.z, fmaf(c.y, c.y, c.x*c.x));
            const float d0 = fmaf(q0x, c.x, fmaf(q0y, c.y, fmaf(q0z, c.z, cc)));
            const float d1 = fmaf(q1x, c.x, fmaf(q1y, c.y, fmaf(q1z, c.z, cc)));
            unsigned m0 = __ballot_sync(FULLM, d0 < kth0);
            unsigned m1 = __ballot_sync(FULLM, d1 < kth1);
            while (m0) {
                const int src = __ffs(m0) - 1; m0 &= m0 - 1;
                const float dn = __shfl_sync(FULLM, d0, src);
                if (dn < kth0) {
                    const int jn = __shfl_sync(FULLM, __float_as_int(c.w), src);
                    const unsigned le = __ballot_sync(FULLM, kd <= dn) & 0xffffu;
                    const int pos = __popc(le);
                    const float kdp = __shfl_up_sync(FULLM, kd, 1);
                    const int   kip = __shfl_up_sync(FULLM, ki, 1);
                    const bool ins = (lane == pos);
                    const bool shf = (lane > pos) && (lane < KNB);
                    kd = ins ? dn : (shf ? kdp : kd);
                    ki = ins ? jn : (shf ? kip : ki);
                    kth0 = __shfl_sync(FULLM, kd, 15);
                }
            }
            while (m1) {
                const int src = __ffs(m1) - 1; m1 &= m1 - 1;
                const float dn = __shfl_sync(FULLM, d1, src);
                if (dn < kth1) {
                    const int jn = __shfl_sync(FULLM, __float_as_int(c.w), src);
                    const unsigned hi = __ballot_sync(FULLM, kd <= dn) & 0xffff0000u;
                    const int pos = 16 + __popc(hi);
                    const float kdp = __shfl_up_sync(FULLM, kd, 1);
                    const int   kip = __shfl_up_sync(FULLM, ki, 1);
                    const bool ins = (lane == pos);
                    const bool shf = (lane > pos);
                    kd = ins ? dn : (shf ? kdp : kd);
                    ki = ins ? jn : (shf ? kip : ki);
                    kth1 = __shfl_sync(FULLM, kd, 31);
                }
            }
            r = rn;
            if (!rmore) rAct = false;
            else {
                // all positions >= rn have bin >= bin(lane31 of processed chunk)
                const int bb = binof(__shfl_sync(FULLM, c.x, 31));
                const float edge = (bb == 0) ? -1.0e30f
                                             : ((float)bb * 0.03125f - 4.0f - 1e-5f);
                const float dxa = edge - qa.x;
                const float dxb = edge - qb.x;
                const bool a0 = (dxa <= 0.f) || (dxa*dxa < kth0 + qaw);
                const bool a1 = (dxb <= 0.f) || (dxb*dxb < kth1 + qbw);
                rAct = a0 || a1;
            }
        }
        // -------- left chunk --------
        if (lAct) {
            const float4 c = cL;
            const int ln = l - CHK;
            const bool lmore = (ln >= 0);
            if (lmore) cL = sc[ln + lane];            // prefetch next
            const float cc = fmaf(c.z, c.z, fmaf(c.y, c.y, c.x*c.x));
            const float d0 = fmaf(q0x, c.x, fmaf(q0y, c.y, fmaf(q0z, c.z, cc)));
            const float d1 = fmaf(q1x, c.x, fmaf(q1y, c.y, fmaf(q1z, c.z, cc)));
            unsigned m0 = __ballot_sync(FULLM, d0 < kth0);
            unsigned m1 = __ballot_sync(FULLM, d1 < kth1);
            while (m0) {
                const int src = __ffs(m0) - 1; m0 &= m0 - 1;
                const float dn = __shfl_sync(FULLM, d0, src);
                if (dn < kth0) {
                    const int jn = __shfl_sync(FULLM, __float_as_int(c.w), src);
                    const unsigned le = __ballot_sync(FULLM, kd <= dn) & 0xffffu;
                    const int pos = __popc(le);
                    const float kdp = __shfl_up_sync(FULLM, kd, 1);
                    const int   kip = __shfl_up_sync(FULLM, ki, 1);
                    const bool ins = (lane == pos);
                    const bool shf = (lane > pos) && (lane < KNB);
                    kd = ins ? dn : (shf ? kdp : kd);
                    ki = ins ? jn : (shf ? kip : ki);
                    kth0 = __shfl_sync(FULLM, kd, 15);
                }
            }
            while (m1) {
                const int src = __ffs(m1) - 1; m1 &= m1 - 1;
                const float dn = __shfl_sync(FULLM, d1, src);
                if (dn < kth1) {
                    const int jn = __shfl_sync(FULLM, __float_as_int(c.w), src);
                    const unsigned hi = __ballot_sync(FULLM, kd <= dn) & 0xffff0000u;
                    const int pos = 16 + __popc(hi);
                    const float kdp = __shfl_up_sync(FULLM, kd, 1);
                    const int   kip = __shfl_up_sync(FULLM, ki, 1);
                    const bool ins = (lane == pos);
                    const bool shf = (lane > pos);
                    kd = ins ? dn : (shf ? kdp : kd);
                    ki = ins ? jn : (shf ? kip : ki);
                    kth1 = __shfl_sync(FULLM, kd, 31);
                }
            }
            l = ln;
            if (!lmore) lAct = false;
            else {
                // all positions <= ln+CHK-1 have bin <= bin(lane0 of processed chunk)
                const int bb = binof(__shfl_sync(FULLM, c.x, 0));
                const float edge = (bb == NBIN-1) ? 1.0e30f
                                                  : ((float)(bb+1) * 0.03125f - 4.0f + 1e-5f);
                const float dxa = qa.x - edge;
                const float dxb = qb.x - edge;
                const bool a0 = (dxa <= 0.f) || (dxa*dxa < kth0 + qaw);
                const bool a1 = (dxb <= 0.f) || (dxb*dxb < kth1 + qbw);
                lAct = a0 || a1;
            }
        }
    }

    const int qq = (lane >> 4) ? q1i : q0i;
    g_knn[((size_t)(batch*NN + qq))*KNB + (lane & 15)] = ki;
}

// ---------------- gather + mean: one warp per point ----------------
__global__ void __launch_bounds__(256) k_gather(const float* __restrict__ feats)
{
    const int row  = blockIdx.x * 8 + (threadIdx.x >> 5);
    const int lane = threadIdx.x & 31;
    const int b = row >> 13;
    const float* fb = feats + (size_t)b * NN * CIN;
    const int* ip = g_knn + (size_t)row * KNB;

    float2 acc = make_float2(0.f, 0.f);
#pragma unroll
    for (int m = 0; m < KNB; ++m) {
        const int id = ip[m];
        const float2 v = ((const float2*)(fb + (size_t)id * CIN))[lane];
        acc.x += v.x; acc.y += v.y;
    }
    ((float2*)(g_X + (size_t)row * CIN))[lane] =
        make_float2(acc.x * (1.0f/KNB), acc.y * (1.0f/KNB));
}

// ---------------- warp sum ----------------
__device__ __forceinline__ float warp_sum(float v) {
#pragma unroll
    for (int o = 16; o; o >>= 1) v += __shfl_xor_sync(FULLM, v, o);
    return v;
}

// ---------------- MLP1: channel-split x4, chunked x ----------------
__global__ void __launch_bounds__(128) k_mlp1(const float* __restrict__ W,
                                              const float* __restrict__ bias)
{
    __shared__ float Ws[CIN*16];
    __shared__ float wsum[4][16], wsq[4][16];
    const int tid = threadIdx.x;
    const int cg = blockIdx.y;
    for (int i = tid; i < CIN*16; i += 128) {
        const int k = i >> 4, c = i & 15;
        Ws[i] = W[k*MID + cg*16 + c];
    }
    __syncthreads();

    const int r = blockIdx.x * 128 + tid;
    const float4* xp = (const float4*)(g_X + (size_t)r * CIN);
    const float4* W4 = (const float4*)Ws;
    const float4* b4 = (const float4*)(bias + cg*16);

    float4 acc[4];
#pragma unroll
    for (int g = 0; g < 4; ++g) acc[g] = b4[g];

#pragma unroll
    for (int kk = 0; kk < CIN/16; ++kk) {
        float xc[16];
#pragma unroll
        for (int u = 0; u < 4; ++u) {
            const float4 v = xp[kk*4+u];
            xc[4*u]=v.x; xc[4*u+1]=v.y; xc[4*u+2]=v.z; xc[4*u+3]=v.w;
        }
#pragma unroll
        for (int j = 0; j < 16; ++j) {
            const int k = kk*16 + j;
            const float xs = xc[j];
#pragma unroll
            for (int g = 0; g < 4; ++g) {
                const float4 w = W4[k*4+g];
                acc[g].x = fmaf(xs, w.x, acc[g].x);
                acc[g].y = fmaf(xs, w.y, acc[g].y);
                acc[g].z = fmaf(xs, w.z, acc[g].z);
                acc[g].w = fmaf(xs, w.w, acc[g].w);
            }
        }
    }

    const int warp = tid >> 5, lane = tid & 31;
    float4* yp = (float4*)(g_Y1 + (size_t)r * MID + cg*16);
#pragma unroll
    for (int g = 0; g < 4; ++g) {
        yp[g] = acc[g];
        const float vs[4] = {acc[g].x, acc[g].y, acc[g].z, acc[g].w};
#pragma unroll
        for (int u = 0; u < 4; ++u) {
            const float s = warp_sum(vs[u]);
            const float qq = warp_sum(vs[u]*vs[u]);
            if (lane == 0) { wsum[warp][4*g+u] = s; wsq[warp][4*g+u] = qq; }
        }
    }
    __syncthreads();
    if (tid < 16) {
        g_Ps1[blockIdx.x*MID + cg*16 + tid] = wsum[0][tid]+wsum[1][tid]+wsum[2][tid]+wsum[3][tid];
        g_Pq1[blockIdx.x*MID + cg*16 + tid] = wsq [0][tid]+wsq [1][tid]+wsq [2][tid]+wsq [3][tid];
    }
}

// ---------------- BN stats finalize ----------------
__device__ __forceinline__ void stats_mid(const float* Ps, const float* Pq,
                                          const float* g, const float* be,
                                          float* A, float* C)
{
    __shared__ float ss[256], sq[256];
    const int tid = threadIdx.x;
    const int c = tid & (MID-1);
    const int grp = tid >> 6;
    float s = 0.f, q = 0.f;
    const int i0 = grp * 64;
#pragma unroll 4
    for (int i = i0; i < i0 + 64; ++i) { s += Ps[i*MID+c]; q += Pq[i*MID+c]; }
    ss[tid] = s; sq[tid] = q;
    __syncthreads();
    if (tid < MID) {
        s = ss[tid] + ss[tid+64] + ss[tid+128] + ss[tid+192];
        q = sq[tid] + sq[tid+64] + sq[tid+128] + sq[tid+192];
        const float m = s / (float)ROWS;
        const float v = q / (float)ROWS - m*m;
        const float a = g[tid] / sqrtf(v + EPSBN);
        A[tid] = a; C[tid] = be[tid] - m*a;
    }
}
__global__ void k_stats1(const float* __restrict__ g, const float* __restrict__ be)
{ stats_mid(g_Ps1, g_Pq1, g, be, g_A1, g_C1); }
__global__ void k_statsa(const float* __restrict__ g, const float* __restrict__ be)
{ stats_mid(g_Psa, g_Pqa, g, be, g_Aa, g_Ca); }

__global__ void k_stats2(const float* __restrict__ g, const float* __restrict__ be)
{
    __shared__ float ss[512], sq[512];
    const int tid = threadIdx.x;
    const int c = tid & (COUT-1);
    const int grp = tid >> 7;
    float s = 0.f, q = 0.f;
    const int i0 = grp * 64;
#pragma unroll 4
    for (int i = i0; i < i0 + 64; ++i) { s += g_Ps2[i*COUT+c]; q += g_Pq2[i*COUT+c]; }
    ss[tid] = s; sq[tid] = q;
    __syncthreads();
    if (tid < COUT) {
        s = ss[tid] + ss[tid+128] + ss[tid+256] + ss[tid+384];
        q = sq[tid] + sq[tid+128] + sq[tid+256] + sq[tid+384];
        const float m = s / (float)ROWS;
        const float v = q / (float)ROWS - m*m;
        const float a = g[tid] / sqrtf(v + EPSBN);
        g_A2[tid] = a; g_C2[tid] = be[tid] - m*a;
    }
}

// ---------------- MLPa: channel-split x4, chunked x ----------------
__global__ void __launch_bounds__(128) k_mlpa(const float* __restrict__ W,
                                              const float* __restrict__ bias)
{
    __shared__ float Ws[MID*16];
    __shared__ float wsum[4][16], wsq[4][16];
    const int tid = threadIdx.x;
    const int cg = blockIdx.y;
    for (int i = tid; i < MID*16; i += 128) {
        const int k = i >> 4, c = i & 15;
        Ws[i] = W[k*MID + cg*16 + c];
    }
    __syncthreads();

    const int r = blockIdx.x * 128 + tid;
    const float4* yin = (const float4*)(g_Y1 + (size_t)r * MID);
    float4* ap = (float4*)(g_Ag + (size_t)r * MID);
    const float4* W4 = (const float4*)Ws;
    const float4* b4 = (const float4*)(bias + cg*16);

    float4 acc[4];
#pragma unroll
    for (int g = 0; g < 4; ++g) acc[g] = b4[g];

#pragma unroll
    for (int kk = 0; kk < MID/16; ++kk) {
        float xc[16];
#pragma unroll
        for (int u = 0; u < 4; ++u) {
            const int i = kk*4 + u;
            const float4 v = yin[i];
            float z0 = fmaxf(fmaf(g_A1[4*i+0], v.x, g_C1[4*i+0]), 0.f);
            float z1 = fmaxf(fmaf(g_A1[4*i+1], v.y, g_C1[4*i+1]), 0.f);
            float z2 = fmaxf(fmaf(g_A1[4*i+2], v.z, g_C1[4*i+2]), 0.f);
            float z3 = fmaxf(fmaf(g_A1[4*i+3], v.w, g_C1[4*i+3]), 0.f);
            if (cg == 0) ap[i] = make_float4(z0, z1, z2, z3);
            xc[4*u]=z0; xc[4*u+1]=z1; xc[4*u+2]=z2; xc[4*u+3]=z3;
        }
#pragma unroll
        for (int j = 0; j < 16; ++j) {
            const int k = kk*16 + j;
            const float xs = xc[j];
#pragma unroll
            for (int g = 0; g < 4; ++g) {
                const float4 w = W4[k*4+g];
                acc[g].x = fmaf(xs, w.x, acc[g].x);
                acc[g].y = fmaf(xs, w.y, acc[g].y);
                acc[g].z = fmaf(xs, w.z, acc[g].z);
                acc[g].w = fmaf(xs, w.w, acc[g].w);
            }
        }
    }

    const int warp = tid >> 5, lane = tid & 31;
    float4* yp = (float4*)(g_Ya + (size_t)r * MID + cg*16);
#pragma unroll
    for (int g = 0; g < 4; ++g) {
        yp[g] = acc[g];
        const float vs[4] = {acc[g].x, acc[g].y, acc[g].z, acc[g].w};
#pragma unroll
        for (int u = 0; u < 4; ++u) {
            const float s = warp_sum(vs[u]);
            const float qq = warp_sum(vs[u]*vs[u]);
            if (lane == 0) { wsum[warp][4*g+u] = s; wsq[warp][4*g+u] = qq; }
        }
    }
    __syncthreads();
    if (tid < 16) {
        g_Psa[blockIdx.x*MID + cg*16 + tid] = wsum[0][tid]+wsum[1][tid]+wsum[2][tid]+wsum[3][tid];
        g_Pqa[blockIdx.x*MID + cg*16 + tid] = wsq [0][tid]+wsq [1][tid]+wsq [2][tid]+wsq [3][tid];
    }
}

// ---------------- MLP2: channel-split x4, chunked x ----------------
__global__ void __launch_bounds__(128) k_mlp2(const float* __restrict__ W,
                                              const float* __restrict__ bias)
{
    __shared__ float Ws[MID*32];
    __shared__ float wsum[4][32], wsq[4][32];
    const int tid = threadIdx.x;
    const int cg = blockIdx.y;
    for (int i = tid; i < MID*32; i += 128) {
        const int k = i >> 5, c = i & 31;
        Ws[i] = W[k*COUT + cg*32 + c];
    }
    __syncthreads();

    const int r = blockIdx.x * 128 + tid;
    const float4* yin = (const float4*)(g_Ya + (size_t)r * MID);
    const float4* ain = (const float4*)(g_Ag + (size_t)r * MID);
    const float4* W4 = (const float4*)Ws;
    const float4* b4 = (const float4*)(bias + cg*32);

    float4 acc[8];
#pragma unroll
    for (int g = 0; g < 8; ++g) acc[g] = b4[g];

#pragma unroll
    for (int kk = 0; kk < MID/16; ++kk) {
        float xc[16];
#pragma unroll
        for (int u = 0; u < 4; ++u) {
            const int i = kk*4 + u;
            const float4 y = yin[i];
            const float4 a = ain[i];
            float t0 = fmaxf(fmaf(g_Aa[4*i+0], y.x, g_Ca[4*i+0]), 0.f);
            float t1 = fmaxf(fmaf(g_Aa[4*i+1], y.y, g_Ca[4*i+1]), 0.f);
            float t2 = fmaxf(fmaf(g_Aa[4*i+2], y.z, g_Ca[4*i+2]), 0.f);
            float t3 = fmaxf(fmaf(g_Aa[4*i+3], y.w, g_Ca[4*i+3]), 0.f);
            float s0 = 1.0f / (1.0f + expf(-t0));
            float s1 = 1.0f / (1.0f + expf(-t1));
            float s2 = 1.0f / (1.0f + expf(-t2));
            float s3 = 1.0f / (1.0f + expf(-t3));
            xc[4*u+0] = fmaf(a.x, s0, a.x);
            xc[4*u+1] = fmaf(a.y, s1, a.y);
            xc[4*u+2] = fmaf(a.z, s2, a.z);
            xc[4*u+3] = fmaf(a.w, s3, a.w);
        }
#pragma unroll
        for (int j = 0; j < 16; ++j) {
            const int k = kk*16 + j;
            const float xs = xc[j];
#pragma unroll
            for (int g = 0; g < 8; ++g) {
                const float4 w = W4[k*8+g];
                acc[g].x = fmaf(xs, w.x, acc[g].x);
                acc[g].y = fmaf(xs, w.y, acc[g].y);
                acc[g].z = fmaf(xs, w.z, acc[g].z);
                acc[g].w = fmaf(xs, w.w, acc[g].w);
            }
        }
    }

    const int warp = tid >> 5, lane = tid & 31;
    float4* yp = (float4*)(g_Y2 + (size_t)r * COUT + cg*32);
#pragma unroll
    for (int g = 0; g < 8; ++g) {
        yp[g] = acc[g];
        const float vs[4] = {acc[g].x, acc[g].y, acc[g].z, acc[g].w};
#pragma unroll
        for (int u = 0; u < 4; ++u) {
            const float s = warp_sum(vs[u]);
            const float qq = warp_sum(vs[u]*vs[u]);
            if (lane == 0) { wsum[warp][4*g+u] = s; wsq[warp][4*g+u] = qq; }
        }
    }
    __syncthreads();
    if (tid < 32) {
        g_Ps2[blockIdx.x*COUT + cg*32 + tid] = wsum[0][tid]+wsum[1][tid]+wsum[2][tid]+wsum[3][tid];
        g_Pq2[blockIdx.x*COUT + cg*32 + tid] = wsq [0][tid]+wsq [1][tid]+wsq [2][tid]+wsq [3][tid];
    }
}

// ---------------- final ----------------
__global__ void __launch_bounds__(256) k_final(float* __restrict__ out)
{
    const int i = blockIdx.x * 256 + threadIdx.x;
    const int c = i & (COUT-1);
    out[i] = fmaxf(fmaf(g_A2[c], g_Y2[i], g_C2[c]), 0.f);
}

// ---------------- launch ----------------
extern "C" void kernel_launch(void* const* d_in, const int* in_sizes, int n_in,
                              void* d_out, int out_size)
{
    const float* coords = (const float*)d_in[0];
    const float* feats  = (const float*)d_in[1];
    const float* W1  = (const float*)d_in[3];
    const float* b1  = (const float*)d_in[4];
    const float* g1  = (const float*)d_in[5];
    const float* be1 = (const float*)d_in[6];
    const float* Wa  = (const float*)d_in[7];
    const float* ba  = (const float*)d_in[8];
    const float* ga  = (const float*)d_in[9];
    const float* bea = (const float*)d_in[10];
    const float* W2  = (const float*)d_in[11];
    const float* b2  = (const float*)d_in[12];
    const float* g2  = (const float*)d_in[13];
    const float* be2 = (const float*)d_in[14];
    float* out = (float*)d_out;

    k_prepcount<<<ROWS/256, 256>>>(coords);
    k_binscan  <<<BB, NBIN>>>();
    k_scatter  <<<ROWS/256, 256>>>();
    k_knn      <<<dim3(NN/16, BB), 256>>>();   // launch #4 -> profiled
    k_gather   <<<ROWS/8, 256>>>(feats);
    k_mlp1     <<<dim3(256, 4), 128>>>(W1, b1);
    k_stats1   <<<1, 256>>>(g1, be1);
    k_mlpa     <<<dim3(256, 4), 128>>>(Wa, ba);
    k_statsa   <<<1, 256>>>(ga, bea);
    k_mlp2     <<<dim3(256, 4), 128>>>(W2, b2);
    k_stats2   <<<1, 512>>>(g2, be2);
    k_final    <<<(ROWS*COUT)/256, 256>>>(out);
}